// round 5
// baseline (speedup 1.0000x reference)
#include <cuda_runtime.h>
#include <cuda_bf16.h>

// LSTMModel: B=1024, T=1024, IN=1, H=20, OUT=2, 3 layers + final FC on last h.
// Strategy: warp = 2 batch elements, lane j (0..19) = hidden unit j.
// All hidden state in registers; h broadcast via __shfl_sync; weights in SMEM
// packed float4 {i,f,g,o}[k][j] so one LDS.128 feeds 8 FFMAs (4 gates x 2 batches).
// No __syncthreads in the timestep loop. FFMA-issue bound by design.

#define B_TOT 1024
#define T_LEN 1024
#define HID   20
#define FULLM 0xffffffffu

// ---- fast activations (MUFU EX2 + RCP based, ~1e-6 rel err) ----
__device__ __forceinline__ float fsig(float x) {
    // 1/(1+exp(-x)); exp overflow for very negative x -> inf -> result 0 (correct)
    float e = __expf(-x);
    return __fdividef(1.0f, 1.0f + e);
}
__device__ __forceinline__ float ftanh(float x) {
    // tanh(x) = sign(x) * (1-e)/(1+e), e = exp(-2|x|) in (0,1] -> no overflow/NaN
    float ax = fabsf(x);
    float e  = __expf(-2.0f * ax);
    float r  = __fdividef(1.0f - e, 1.0f + e);
    return copysignf(r, x);
}

__global__ void __launch_bounds__(64)
lstm3_kernel(const float* __restrict__ x,
             const float* __restrict__ wih0, const float* __restrict__ whh0,
             const float* __restrict__ bih0, const float* __restrict__ bhh0,
             const float* __restrict__ wih1, const float* __restrict__ whh1,
             const float* __restrict__ bih1, const float* __restrict__ bhh1,
             const float* __restrict__ wih2, const float* __restrict__ whh2,
             const float* __restrict__ bih2, const float* __restrict__ bhh2,
             const float* __restrict__ fcw,  const float* __restrict__ fcb,
             float* __restrict__ out)
{
    // SMEM weight layout: s_*[k][j] = {w[j][k], w[j+20][k], w[j+40][k], w[j+60][k]}
    __shared__ float4 s_whh0[HID][HID];       // L0 recurrent  (k: 0..19)
    __shared__ float4 s_w1[2 * HID][HID];     // L1: k<20 -> w_ih1, k>=20 -> w_hh1
    __shared__ float4 s_w2[2 * HID][HID];     // L2 same
    __shared__ float4 s_wx0[HID];             // w_ih0 column (IN=1), 4 gates
    __shared__ float4 s_b0[HID], s_b1[HID], s_b2[HID];  // b_ih + b_hh per gate
    __shared__ float  s_fcw[2][HID];
    __shared__ float  s_fcb[2];

    const int tid = threadIdx.x;

    // ---- stage weights into SMEM (once per block) ----
    for (int idx = tid; idx < HID * HID; idx += 64) {
        int k = idx / HID, j = idx % HID;
        s_whh0[k][j] = make_float4(whh0[(j     ) * HID + k],
                                   whh0[(j + 20) * HID + k],
                                   whh0[(j + 40) * HID + k],
                                   whh0[(j + 60) * HID + k]);
    }
    for (int idx = tid; idx < 2 * HID * HID; idx += 64) {
        int k = idx / HID, j = idx % HID;
        const float* wsrc1 = (k < HID) ? wih1 : whh1;
        const float* wsrc2 = (k < HID) ? wih2 : whh2;
        int kk = (k < HID) ? k : (k - HID);
        s_w1[k][j] = make_float4(wsrc1[(j     ) * HID + kk],
                                 wsrc1[(j + 20) * HID + kk],
                                 wsrc1[(j + 40) * HID + kk],
                                 wsrc1[(j + 60) * HID + kk]);
        s_w2[k][j] = make_float4(wsrc2[(j     ) * HID + kk],
                                 wsrc2[(j + 20) * HID + kk],
                                 wsrc2[(j + 40) * HID + kk],
                                 wsrc2[(j + 60) * HID + kk]);
    }
    for (int j = tid; j < HID; j += 64) {
        s_wx0[j] = make_float4(wih0[j], wih0[j + 20], wih0[j + 40], wih0[j + 60]);
        s_b0[j] = make_float4(bih0[j] + bhh0[j],       bih0[j + 20] + bhh0[j + 20],
                              bih0[j + 40] + bhh0[j + 40], bih0[j + 60] + bhh0[j + 60]);
        s_b1[j] = make_float4(bih1[j] + bhh1[j],       bih1[j + 20] + bhh1[j + 20],
                              bih1[j + 40] + bhh1[j + 40], bih1[j + 60] + bhh1[j + 60]);
        s_b2[j] = make_float4(bih2[j] + bhh2[j],       bih2[j + 20] + bhh2[j + 20],
                              bih2[j + 40] + bhh2[j + 40], bih2[j + 60] + bhh2[j + 60]);
    }
    if (tid < 2 * HID) s_fcw[tid / HID][tid % HID] = fcw[tid];
    if (tid < 2)       s_fcb[tid] = fcb[tid];
    __syncthreads();

    const int lane = tid & 31;
    const int warp = tid >> 5;
    const int b0 = blockIdx.x * 4 + warp * 2;   // 2 batches per warp
    const int b1 = b0 + 1;
    const int j  = (lane < HID) ? lane : (HID - 1);  // lanes 20..31 duplicate unit 19

    const float* __restrict__ x0p = x + b0 * T_LEN;
    const float* __restrict__ x1p = x + b1 * T_LEN;

    const float4 wx  = s_wx0[j];
    const float4 bb0 = s_b0[j];
    const float4 bb1 = s_b1[j];
    const float4 bb2 = s_b2[j];

    // per-lane state (registers)
    float h0a = 0.f, c0a = 0.f, h0b = 0.f, c0b = 0.f;
    float h1a = 0.f, c1a = 0.f, h1b = 0.f, c1b = 0.f;
    float h2a = 0.f, c2a = 0.f, h2b = 0.f, c2b = 0.f;

    for (int tb = 0; tb < T_LEN; tb += 32) {
        // coalesced x prefetch: lane s holds x[tb+s]
        float xv0 = x0p[tb + lane];
        float xv1 = x1p[tb + lane];

#pragma unroll 1
        for (int s = 0; s < 32; s++) {
            float xt0 = __shfl_sync(FULLM, xv0, s);
            float xt1 = __shfl_sync(FULLM, xv1, s);

            // ================= layer 0 (K = 20, input is scalar x) =============
            float ai0 = fmaf(xt0, wx.x, bb0.x), af0 = fmaf(xt0, wx.y, bb0.y);
            float ag0 = fmaf(xt0, wx.z, bb0.z), ao0 = fmaf(xt0, wx.w, bb0.w);
            float ai1 = fmaf(xt1, wx.x, bb0.x), af1 = fmaf(xt1, wx.y, bb0.y);
            float ag1 = fmaf(xt1, wx.z, bb0.z), ao1 = fmaf(xt1, wx.w, bb0.w);
#pragma unroll
            for (int k = 0; k < HID; k++) {
                float ha = __shfl_sync(FULLM, h0a, k);
                float hb = __shfl_sync(FULLM, h0b, k);
                float4 w = s_whh0[k][j];
                ai0 = fmaf(ha, w.x, ai0); af0 = fmaf(ha, w.y, af0);
                ag0 = fmaf(ha, w.z, ag0); ao0 = fmaf(ha, w.w, ao0);
                ai1 = fmaf(hb, w.x, ai1); af1 = fmaf(hb, w.y, af1);
                ag1 = fmaf(hb, w.z, ag1); ao1 = fmaf(hb, w.w, ao1);
            }
            c0a = fsig(af0) * c0a + fsig(ai0) * ftanh(ag0);
            h0a = fsig(ao0) * ftanh(c0a);
            c0b = fsig(af1) * c0b + fsig(ai1) * ftanh(ag1);
            h0b = fsig(ao1) * ftanh(c0b);

            // ================= layer 1 (K = 40: h0_new then h1_prev) ===========
            ai0 = bb1.x; af0 = bb1.y; ag0 = bb1.z; ao0 = bb1.w;
            ai1 = bb1.x; af1 = bb1.y; ag1 = bb1.z; ao1 = bb1.w;
#pragma unroll
            for (int k = 0; k < HID; k++) {
                float ha = __shfl_sync(FULLM, h0a, k);
                float hb = __shfl_sync(FULLM, h0b, k);
                float4 w = s_w1[k][j];
                ai0 = fmaf(ha, w.x, ai0); af0 = fmaf(ha, w.y, af0);
                ag0 = fmaf(ha, w.z, ag0); ao0 = fmaf(ha, w.w, ao0);
                ai1 = fmaf(hb, w.x, ai1); af1 = fmaf(hb, w.y, af1);
                ag1 = fmaf(hb, w.z, ag1); ao1 = fmaf(hb, w.w, ao1);
            }
#pragma unroll
            for (int k = 0; k < HID; k++) {
                float ha = __shfl_sync(FULLM, h1a, k);
                float hb = __shfl_sync(FULLM, h1b, k);
                float4 w = s_w1[k + HID][j];
                ai0 = fmaf(ha, w.x, ai0); af0 = fmaf(ha, w.y, af0);
                ag0 = fmaf(ha, w.z, ag0); ao0 = fmaf(ha, w.w, ao0);
                ai1 = fmaf(hb, w.x, ai1); af1 = fmaf(hb, w.y, af1);
                ag1 = fmaf(hb, w.z, ag1); ao1 = fmaf(hb, w.w, ao1);
            }
            c1a = fsig(af0) * c1a + fsig(ai0) * ftanh(ag0);
            h1a = fsig(ao0) * ftanh(c1a);
            c1b = fsig(af1) * c1b + fsig(ai1) * ftanh(ag1);
            h1b = fsig(ao1) * ftanh(c1b);

            // ================= layer 2 (K = 40: h1_new then h2_prev) ===========
            ai0 = bb2.x; af0 = bb2.y; ag0 = bb2.z; ao0 = bb2.w;
            ai1 = bb2.x; af1 = bb2.y; ag1 = bb2.z; ao1 = bb2.w;
#pragma unroll
            for (int k = 0; k < HID; k++) {
                float ha = __shfl_sync(FULLM, h1a, k);
                float hb = __shfl_sync(FULLM, h1b, k);
                float4 w = s_w2[k][j];
                ai0 = fmaf(ha, w.x, ai0); af0 = fmaf(ha, w.y, af0);
                ag0 = fmaf(ha, w.z, ag0); ao0 = fmaf(ha, w.w, ao0);
                ai1 = fmaf(hb, w.x, ai1); af1 = fmaf(hb, w.y, af1);
                ag1 = fmaf(hb, w.z, ag1); ao1 = fmaf(hb, w.w, ao1);
            }
#pragma unroll
            for (int k = 0; k < HID; k++) {
                float ha = __shfl_sync(FULLM, h2a, k);
                float hb = __shfl_sync(FULLM, h2b, k);
                float4 w = s_w2[k + HID][j];
                ai0 = fmaf(ha, w.x, ai0); af0 = fmaf(ha, w.y, af0);
                ag0 = fmaf(ha, w.z, ag0); ao0 = fmaf(ha, w.w, ao0);
                ai1 = fmaf(hb, w.x, ai1); af1 = fmaf(hb, w.y, af1);
                ag1 = fmaf(hb, w.z, ag1); ao1 = fmaf(hb, w.w, ao1);
            }
            c2a = fsig(af0) * c2a + fsig(ai0) * ftanh(ag0);
            h2a = fsig(ao0) * ftanh(c2a);
            c2b = fsig(af1) * c2b + fsig(ai1) * ftanh(ag1);
            h2b = fsig(ao1) * ftanh(c2b);
        }
    }

    // ---- final FC: out[b] = fc_w @ h2 + fc_b (reduce over lanes 0..19) ----
    float w0 = s_fcw[0][j], w1 = s_fcw[1][j];
    float p0a = (lane < HID) ? h2a * w0 : 0.f;
    float p1a = (lane < HID) ? h2a * w1 : 0.f;
    float p0b = (lane < HID) ? h2b * w0 : 0.f;
    float p1b = (lane < HID) ? h2b * w1 : 0.f;
#pragma unroll
    for (int off = 16; off > 0; off >>= 1) {
        p0a += __shfl_xor_sync(FULLM, p0a, off);
        p1a += __shfl_xor_sync(FULLM, p1a, off);
        p0b += __shfl_xor_sync(FULLM, p0b, off);
        p1b += __shfl_xor_sync(FULLM, p1b, off);
    }
    if (lane == 0) {
        out[b0 * 2 + 0] = p0a + s_fcb[0];
        out[b0 * 2 + 1] = p1a + s_fcb[1];
        out[b1 * 2 + 0] = p0b + s_fcb[0];
        out[b1 * 2 + 1] = p1b + s_fcb[1];
    }
}

extern "C" void kernel_launch(void* const* d_in, const int* in_sizes, int n_in,
                              void* d_out, int out_size) {
    const float* x    = (const float*)d_in[0];
    const float* wih0 = (const float*)d_in[1];
    const float* whh0 = (const float*)d_in[2];
    const float* bih0 = (const float*)d_in[3];
    const float* bhh0 = (const float*)d_in[4];
    const float* wih1 = (const float*)d_in[5];
    const float* whh1 = (const float*)d_in[6];
    const float* bih1 = (const float*)d_in[7];
    const float* bhh1 = (const float*)d_in[8];
    const float* wih2 = (const float*)d_in[9];
    const float* whh2 = (const float*)d_in[10];
    const float* bih2 = (const float*)d_in[11];
    const float* bhh2 = (const float*)d_in[12];
    const float* fcw  = (const float*)d_in[13];
    const float* fcb  = (const float*)d_in[14];
    float* out = (float*)d_out;

    // 256 blocks x 64 threads; each block = 2 warps x 2 batches = 4 batches
    lstm3_kernel<<<B_TOT / 4, 64>>>(x, wih0, whh0, bih0, bhh0,
                                    wih1, whh1, bih1, bhh1,
                                    wih2, whh2, bih2, bhh2,
                                    fcw, fcb, out);
}

// round 6
// speedup vs baseline: 1.0027x; 1.0027x over previous
#include <cuda_runtime.h>
#include <cuda_bf16.h>

// 3-layer LSTM, B=1024, T=1024, H=20, IN=1, OUT=2, FC on last h2.
// Warp = 2 batches; lane j (0..19) = hidden unit j (gate rows j, j+20, j+40, j+60).
// Gates accumulated as packed f32x2 pairs {i,f},{g,o} via fma.rn.f32x2 (FFMA2):
//   weights in SMEM as float4 {wi,wf,wg,wo}[k][j] -> two aligned 64-bit pairs, free.
//   h delivered duplicated {h,h} from SMEM: one broadcast LDS.128 feeds 2 k-steps.
// L0 recurrent weights register-cached (loop invariant). No SHFL in hot loop.

#define B_TOT 1024
#define T_LEN 1024
#define HID   20
#define FULLM 0xffffffffu

typedef unsigned long long u64;

__device__ __forceinline__ void ffma2(u64 &acc, u64 a, u64 b) {
    asm("fma.rn.f32x2 %0, %1, %2, %0;" : "+l"(acc) : "l"(a), "l"(b));
}
__device__ __forceinline__ u64 packdup(float f) {
    u64 r; asm("mov.b64 %0, {%1, %1};" : "=l"(r) : "f"(f)); return r;
}
__device__ __forceinline__ void unpack2(float &lo, float &hi, u64 v) {
    asm("mov.b64 {%0, %1}, %2;" : "=f"(lo), "=f"(hi) : "l"(v));
}

// ---- accurate fast activations (MUFU EX2/RCP, ~1e-6 err) ----
__device__ __forceinline__ float fsig(float x) {
    float e = __expf(-x);
    return __fdividef(1.0f, 1.0f + e);
}
__device__ __forceinline__ float ftanh(float x) {
    float ax = fabsf(x);
    float e  = __expf(-2.0f * ax);
    float r  = __fdividef(1.0f - e, 1.0f + e);
    return copysignf(r, x);
}

// gate pair accs -> (new c, returns new h)
__device__ __forceinline__ float cellup(u64 aif, u64 ago, float &c) {
    float ai, af, ag, ao;
    unpack2(ai, af, aif);
    unpack2(ag, ao, ago);
    c = fsig(af) * c + fsig(ai) * ftanh(ag);
    return fsig(ao) * ftanh(c);
}

// 20-step MAC block, weights from SMEM rows w[k][j] (k = 0..19 of this block)
__device__ __forceinline__ void mac20_sm(u64 &aif, u64 &ago, u64 &bif, u64 &bgo,
                                         const float2* __restrict__ hA,
                                         const float2* __restrict__ hB,
                                         const float4 (* __restrict__ w)[HID], int j)
{
#pragma unroll
    for (int m = 0; m < 10; m++) {
        ulonglong2 ha = *(const ulonglong2*)(hA + 2 * m);   // {h2m,h2m},{h2m+1,h2m+1}
        ulonglong2 hb = *(const ulonglong2*)(hB + 2 * m);
        ulonglong2 w0 = *(const ulonglong2*)&w[2 * m][j];   // {wi,wf},{wg,wo}
        ulonglong2 w1 = *(const ulonglong2*)&w[2 * m + 1][j];
        ffma2(aif, ha.x, w0.x); ffma2(ago, ha.x, w0.y);
        ffma2(bif, hb.x, w0.x); ffma2(bgo, hb.x, w0.y);
        ffma2(aif, ha.y, w1.x); ffma2(ago, ha.y, w1.y);
        ffma2(bif, hb.y, w1.x); ffma2(bgo, hb.y, w1.y);
    }
}

__global__ void __launch_bounds__(64)
lstm3_kernel(const float* __restrict__ x,
             const float* __restrict__ wih0, const float* __restrict__ whh0,
             const float* __restrict__ bih0, const float* __restrict__ bhh0,
             const float* __restrict__ wih1, const float* __restrict__ whh1,
             const float* __restrict__ bih1, const float* __restrict__ bhh1,
             const float* __restrict__ wih2, const float* __restrict__ whh2,
             const float* __restrict__ bih2, const float* __restrict__ bhh2,
             const float* __restrict__ fcw,  const float* __restrict__ fcb,
             float* __restrict__ out)
{
    __shared__ float4 s_whh0[HID][HID];        // staging for L0 reg cache
    __shared__ float4 s_w1[2 * HID][HID];      // k<20: w_ih1, k>=20: w_hh1
    __shared__ float4 s_w2[2 * HID][HID];
    __shared__ float4 s_wx0[HID];
    __shared__ float4 s_b0[HID], s_b1[HID], s_b2[HID];
    __shared__ __align__(16) float2 sh_h[2][2][3][HID];  // [warp][batch][layer][j] = {h,h}
    __shared__ float s_fcw[2][HID];
    __shared__ float s_fcb[2];

    const int tid = threadIdx.x;

    // ---- stage weights (transposed, gate-packed) ----
    for (int idx = tid; idx < HID * HID; idx += 64) {
        int k = idx / HID, j = idx % HID;
        s_whh0[k][j] = make_float4(whh0[(j     ) * HID + k],
                                   whh0[(j + 20) * HID + k],
                                   whh0[(j + 40) * HID + k],
                                   whh0[(j + 60) * HID + k]);
    }
    for (int idx = tid; idx < 2 * HID * HID; idx += 64) {
        int k = idx / HID, j = idx % HID;
        const float* w1s = (k < HID) ? wih1 : whh1;
        const float* w2s = (k < HID) ? wih2 : whh2;
        int kk = (k < HID) ? k : (k - HID);
        s_w1[k][j] = make_float4(w1s[(j     ) * HID + kk], w1s[(j + 20) * HID + kk],
                                 w1s[(j + 40) * HID + kk], w1s[(j + 60) * HID + kk]);
        s_w2[k][j] = make_float4(w2s[(j     ) * HID + kk], w2s[(j + 20) * HID + kk],
                                 w2s[(j + 40) * HID + kk], w2s[(j + 60) * HID + kk]);
    }
    for (int j = tid; j < HID; j += 64) {
        s_wx0[j] = make_float4(wih0[j], wih0[j + 20], wih0[j + 40], wih0[j + 60]);
        s_b0[j] = make_float4(bih0[j] + bhh0[j],           bih0[j + 20] + bhh0[j + 20],
                              bih0[j + 40] + bhh0[j + 40], bih0[j + 60] + bhh0[j + 60]);
        s_b1[j] = make_float4(bih1[j] + bhh1[j],           bih1[j + 20] + bhh1[j + 20],
                              bih1[j + 40] + bhh1[j + 40], bih1[j + 60] + bhh1[j + 60]);
        s_b2[j] = make_float4(bih2[j] + bhh2[j],           bih2[j + 20] + bhh2[j + 20],
                              bih2[j + 40] + bhh2[j + 40], bih2[j + 60] + bhh2[j + 60]);
    }
    if (tid < 2 * HID) s_fcw[tid / HID][tid % HID] = fcw[tid];
    if (tid < 2)       s_fcb[tid] = fcb[tid];
    __syncthreads();

    const int lane = tid & 31;
    const int warp = tid >> 5;
    const int b0 = blockIdx.x * 4 + warp * 2;
    const int b1 = b0 + 1;
    const int j  = (lane < HID) ? lane : (HID - 1);   // lanes 20..31 shadow unit 19

    const float* __restrict__ x0p = x + b0 * T_LEN;
    const float* __restrict__ x1p = x + b1 * T_LEN;

    // register-cache L0 recurrent weights + per-lane constants
    ulonglong2 wr0[HID];
#pragma unroll
    for (int k = 0; k < HID; k++) wr0[k] = *(const ulonglong2*)&s_whh0[k][j];
    const ulonglong2 wx = *(const ulonglong2*)&s_wx0[j];
    const ulonglong2 B0 = *(const ulonglong2*)&s_b0[j];
    const ulonglong2 B1 = *(const ulonglong2*)&s_b1[j];
    const ulonglong2 B2 = *(const ulonglong2*)&s_b2[j];

    float2* __restrict__ h0A = sh_h[warp][0][0];
    float2* __restrict__ h1A = sh_h[warp][0][1];
    float2* __restrict__ h2A = sh_h[warp][0][2];
    float2* __restrict__ h0B = sh_h[warp][1][0];
    float2* __restrict__ h1B = sh_h[warp][1][1];
    float2* __restrict__ h2B = sh_h[warp][1][2];

    // init h = 0 (lanes 20..31 write same zero to [19]: benign)
    {
        float2 z = make_float2(0.f, 0.f);
        h0A[j] = z; h1A[j] = z; h2A[j] = z;
        h0B[j] = z; h1B[j] = z; h2B[j] = z;
        __syncwarp();
    }

    float c0a = 0.f, c0b = 0.f, c1a = 0.f, c1b = 0.f, c2a = 0.f, c2b = 0.f;
    float h2a = 0.f, h2b = 0.f;

    for (int tb = 0; tb < T_LEN; tb += 32) {
        float xv0 = x0p[tb + lane];   // coalesced stripe of 32 timesteps
        float xv1 = x1p[tb + lane];

#pragma unroll 1
        for (int s = 0; s < 32; s++) {
            u64 xx0 = packdup(__shfl_sync(FULLM, xv0, s));
            u64 xx1 = packdup(__shfl_sync(FULLM, xv1, s));

            // ---------- layer 0 (K=20, reg-cached weights) ----------
            u64 aif = B0.x, ago = B0.y, bif = B0.x, bgo = B0.y;
            ffma2(aif, xx0, wx.x); ffma2(ago, xx0, wx.y);
            ffma2(bif, xx1, wx.x); ffma2(bgo, xx1, wx.y);
#pragma unroll
            for (int m = 0; m < 10; m++) {
                ulonglong2 ha = *(const ulonglong2*)(h0A + 2 * m);
                ulonglong2 hb = *(const ulonglong2*)(h0B + 2 * m);
                ffma2(aif, ha.x, wr0[2 * m].x);     ffma2(ago, ha.x, wr0[2 * m].y);
                ffma2(bif, hb.x, wr0[2 * m].x);     ffma2(bgo, hb.x, wr0[2 * m].y);
                ffma2(aif, ha.y, wr0[2 * m + 1].x); ffma2(ago, ha.y, wr0[2 * m + 1].y);
                ffma2(bif, hb.y, wr0[2 * m + 1].x); ffma2(bgo, hb.y, wr0[2 * m + 1].y);
            }
            float h0a = cellup(aif, ago, c0a);
            float h0b = cellup(bif, bgo, c0b);
            h0A[j] = make_float2(h0a, h0a);
            h0B[j] = make_float2(h0b, h0b);
            __syncwarp();

            // ---------- layer 1 (K=40: h0_new, h1_prev) ----------
            aif = B1.x; ago = B1.y; bif = B1.x; bgo = B1.y;
            mac20_sm(aif, ago, bif, bgo, h0A, h0B, s_w1, j);
            mac20_sm(aif, ago, bif, bgo, h1A, h1B, s_w1 + HID, j);
            float h1a = cellup(aif, ago, c1a);
            float h1b = cellup(bif, bgo, c1b);
            h1A[j] = make_float2(h1a, h1a);
            h1B[j] = make_float2(h1b, h1b);
            __syncwarp();

            // ---------- layer 2 (K=40: h1_new, h2_prev) ----------
            aif = B2.x; ago = B2.y; bif = B2.x; bgo = B2.y;
            mac20_sm(aif, ago, bif, bgo, h1A, h1B, s_w2, j);
            mac20_sm(aif, ago, bif, bgo, h2A, h2B, s_w2 + HID, j);
            h2a = cellup(aif, ago, c2a);
            h2b = cellup(bif, bgo, c2b);
            h2A[j] = make_float2(h2a, h2a);
            h2B[j] = make_float2(h2b, h2b);
            // h2 is first consumed after next iteration's L1 syncwarp: ordered.
        }
    }

    // ---- final FC: out[b] = fc_w @ h2 + fc_b ----
    float w0 = s_fcw[0][j], w1 = s_fcw[1][j];
    float p0a = (lane < HID) ? h2a * w0 : 0.f;
    float p1a = (lane < HID) ? h2a * w1 : 0.f;
    float p0b = (lane < HID) ? h2b * w0 : 0.f;
    float p1b = (lane < HID) ? h2b * w1 : 0.f;
#pragma unroll
    for (int off = 16; off > 0; off >>= 1) {
        p0a += __shfl_xor_sync(FULLM, p0a, off);
        p1a += __shfl_xor_sync(FULLM, p1a, off);
        p0b += __shfl_xor_sync(FULLM, p0b, off);
        p1b += __shfl_xor_sync(FULLM, p1b, off);
    }
    if (lane == 0) {
        out[b0 * 2 + 0] = p0a + s_fcb[0];
        out[b0 * 2 + 1] = p1a + s_fcb[1];
        out[b1 * 2 + 0] = p0b + s_fcb[0];
        out[b1 * 2 + 1] = p1b + s_fcb[1];
    }
}

extern "C" void kernel_launch(void* const* d_in, const int* in_sizes, int n_in,
                              void* d_out, int out_size) {
    const float* x    = (const float*)d_in[0];
    const float* wih0 = (const float*)d_in[1];
    const float* whh0 = (const float*)d_in[2];
    const float* bih0 = (const float*)d_in[3];
    const float* bhh0 = (const float*)d_in[4];
    const float* wih1 = (const float*)d_in[5];
    const float* whh1 = (const float*)d_in[6];
    const float* bih1 = (const float*)d_in[7];
    const float* bhh1 = (const float*)d_in[8];
    const float* wih2 = (const float*)d_in[9];
    const float* whh2 = (const float*)d_in[10];
    const float* bih2 = (const float*)d_in[11];
    const float* bhh2 = (const float*)d_in[12];
    const float* fcw  = (const float*)d_in[13];
    const float* fcb  = (const float*)d_in[14];
    float* out = (float*)d_out;

    lstm3_kernel<<<B_TOT / 4, 64>>>(x, wih0, whh0, bih0, bhh0,
                                    wih1, whh1, bih1, bhh1,
                                    wih2, whh2, bih2, bhh2,
                                    fcw, fcb, out);
}

// round 7
// speedup vs baseline: 1.0652x; 1.0623x over previous
#include <cuda_runtime.h>
#include <cuda_bf16.h>

// 3-layer LSTM, B=1024, T=1024, H=20, IN=1, OUT=2, FC on last h2.
// R7: 1 batch per warp (1024 warps; grid 148 x 7 warps -> balanced 7 warps/SM)
// to fix the 0.87-warp/SMSP latency bound seen in R5/R6.
// Lane j (0..19) = hidden unit j; gates packed {i,f},{g,o}, fma.rn.f32x2.
// Reg-cached weights: L0 recurrent (20 k) + L1 first half (h0 input, 20 k)
// = 160 regs, so smem weight loads are only 60 LDS.128/warp/timestep.

#define B_TOT 1024
#define T_LEN 1024
#define HID   20
#define FULLM 0xffffffffu
#define WARPS_PER_BLOCK 7
#define NBLOCKS 148

typedef unsigned long long u64;

__device__ __forceinline__ void ffma2(u64 &acc, u64 a, u64 b) {
    asm("fma.rn.f32x2 %0, %1, %2, %0;" : "+l"(acc) : "l"(a), "l"(b));
}
__device__ __forceinline__ u64 packdup(float f) {
    u64 r; asm("mov.b64 %0, {%1, %1};" : "=l"(r) : "f"(f)); return r;
}
__device__ __forceinline__ void unpack2(float &lo, float &hi, u64 v) {
    asm("mov.b64 {%0, %1}, %2;" : "=f"(lo), "=f"(hi) : "l"(v));
}

// ---- accurate fast activations (MUFU EX2/RCP, ~1e-6 err) ----
__device__ __forceinline__ float fsig(float x) {
    float e = __expf(-x);
    return __fdividef(1.0f, 1.0f + e);
}
__device__ __forceinline__ float ftanh(float x) {
    float ax = fabsf(x);
    float e  = __expf(-2.0f * ax);
    float r  = __fdividef(1.0f - e, 1.0f + e);
    return copysignf(r, x);
}

// gate pair accs -> updates c, returns new h
__device__ __forceinline__ float cellup(u64 aif, u64 ago, float &c) {
    float ai, af, ag, ao;
    unpack2(ai, af, aif);
    unpack2(ag, ao, ago);
    c = fsig(af) * c + fsig(ai) * ftanh(ag);
    return fsig(ao) * ftanh(c);
}

// 20 k-steps, weights register-resident
__device__ __forceinline__ void mac10_reg(u64 &aif, u64 &ago,
                                          const float2* __restrict__ h,
                                          const ulonglong2* __restrict__ wr)
{
#pragma unroll
    for (int m = 0; m < 10; m++) {
        ulonglong2 hh = *(const ulonglong2*)(h + 2 * m);   // {h2m,h2m},{h2m+1,h2m+1}
        ffma2(aif, hh.x, wr[2 * m].x);     ffma2(ago, hh.x, wr[2 * m].y);
        ffma2(aif, hh.y, wr[2 * m + 1].x); ffma2(ago, hh.y, wr[2 * m + 1].y);
    }
}

// 20 k-steps, weights from SMEM rows w[k][j]
__device__ __forceinline__ void mac10_sm(u64 &aif, u64 &ago,
                                         const float2* __restrict__ h,
                                         const float4 (* __restrict__ w)[HID], int j)
{
#pragma unroll
    for (int m = 0; m < 10; m++) {
        ulonglong2 hh = *(const ulonglong2*)(h + 2 * m);
        ulonglong2 w0 = *(const ulonglong2*)&w[2 * m][j];   // {wi,wf},{wg,wo}
        ulonglong2 w1 = *(const ulonglong2*)&w[2 * m + 1][j];
        ffma2(aif, hh.x, w0.x); ffma2(ago, hh.x, w0.y);
        ffma2(aif, hh.y, w1.x); ffma2(ago, hh.y, w1.y);
    }
}

__global__ void __launch_bounds__(WARPS_PER_BLOCK * 32)
lstm3_kernel(const float* __restrict__ x,
             const float* __restrict__ wih0, const float* __restrict__ whh0,
             const float* __restrict__ bih0, const float* __restrict__ bhh0,
             const float* __restrict__ wih1, const float* __restrict__ whh1,
             const float* __restrict__ bih1, const float* __restrict__ bhh1,
             const float* __restrict__ wih2, const float* __restrict__ whh2,
             const float* __restrict__ bih2, const float* __restrict__ bhh2,
             const float* __restrict__ fcw,  const float* __restrict__ fcb,
             float* __restrict__ out)
{
    __shared__ float4 s_whh0[HID][HID];      // staged, then reg-cached (L0)
    __shared__ float4 s_w1a[HID][HID];       // staged, then reg-cached (L1, h0 half)
    __shared__ float4 s_w1b[HID][HID];       // L1, h1 half (hot smem)
    __shared__ float4 s_w2[2 * HID][HID];    // L2 both halves (hot smem)
    __shared__ float4 s_wx0[HID];
    __shared__ float4 s_b0[HID], s_b1[HID], s_b2[HID];
    __shared__ __align__(16) float2 sh_h[WARPS_PER_BLOCK][3][HID];  // {h,h} dup
    __shared__ float s_fcw[2][HID];
    __shared__ float s_fcb[2];

    const int tid = threadIdx.x;
    const int nthr = WARPS_PER_BLOCK * 32;

    // ---- stage weights (transposed, gate-packed) ----
    for (int idx = tid; idx < HID * HID; idx += nthr) {
        int k = idx / HID, j = idx % HID;
        s_whh0[k][j] = make_float4(whh0[(j     ) * HID + k], whh0[(j + 20) * HID + k],
                                   whh0[(j + 40) * HID + k], whh0[(j + 60) * HID + k]);
        s_w1a[k][j]  = make_float4(wih1[(j     ) * HID + k], wih1[(j + 20) * HID + k],
                                   wih1[(j + 40) * HID + k], wih1[(j + 60) * HID + k]);
        s_w1b[k][j]  = make_float4(whh1[(j     ) * HID + k], whh1[(j + 20) * HID + k],
                                   whh1[(j + 40) * HID + k], whh1[(j + 60) * HID + k]);
    }
    for (int idx = tid; idx < 2 * HID * HID; idx += nthr) {
        int k = idx / HID, j = idx % HID;
        const float* w2s = (k < HID) ? wih2 : whh2;
        int kk = (k < HID) ? k : (k - HID);
        s_w2[k][j] = make_float4(w2s[(j     ) * HID + kk], w2s[(j + 20) * HID + kk],
                                 w2s[(j + 40) * HID + kk], w2s[(j + 60) * HID + kk]);
    }
    for (int j = tid; j < HID; j += nthr) {
        s_wx0[j] = make_float4(wih0[j], wih0[j + 20], wih0[j + 40], wih0[j + 60]);
        s_b0[j] = make_float4(bih0[j] + bhh0[j],           bih0[j + 20] + bhh0[j + 20],
                              bih0[j + 40] + bhh0[j + 40], bih0[j + 60] + bhh0[j + 60]);
        s_b1[j] = make_float4(bih1[j] + bhh1[j],           bih1[j + 20] + bhh1[j + 20],
                              bih1[j + 40] + bhh1[j + 40], bih1[j + 60] + bhh1[j + 60]);
        s_b2[j] = make_float4(bih2[j] + bhh2[j],           bih2[j + 20] + bhh2[j + 20],
                              bih2[j + 40] + bhh2[j + 40], bih2[j + 60] + bhh2[j + 60]);
    }
    if (tid < 2 * HID) s_fcw[tid / HID][tid % HID] = fcw[tid];
    if (tid < 2)       s_fcb[tid] = fcb[tid];
    __syncthreads();

    const int lane = tid & 31;
    const int warp = tid >> 5;
    const int b = blockIdx.x * WARPS_PER_BLOCK + warp;   // 1 batch per warp
    if (b >= B_TOT) return;                              // 12 idle warps (after sync)
    const int j = (lane < HID) ? lane : (HID - 1);       // lanes 20..31 shadow unit 19

    const float* __restrict__ xp = x + b * T_LEN;

    // ---- register-cache L0 recurrent + L1 h0-half weights (160 regs) ----
    ulonglong2 wr0[HID], wr1[HID];
#pragma unroll
    for (int k = 0; k < HID; k++) {
        wr0[k] = *(const ulonglong2*)&s_whh0[k][j];
        wr1[k] = *(const ulonglong2*)&s_w1a[k][j];
    }
    const ulonglong2 wx = *(const ulonglong2*)&s_wx0[j];
    const ulonglong2 B0 = *(const ulonglong2*)&s_b0[j];
    const ulonglong2 B1 = *(const ulonglong2*)&s_b1[j];
    const ulonglong2 B2 = *(const ulonglong2*)&s_b2[j];

    float2* __restrict__ h0s = sh_h[warp][0];
    float2* __restrict__ h1s = sh_h[warp][1];
    float2* __restrict__ h2s = sh_h[warp][2];

    {
        float2 z = make_float2(0.f, 0.f);
        h0s[j] = z; h1s[j] = z; h2s[j] = z;
        __syncwarp();
    }

    float c0 = 0.f, c1 = 0.f, c2 = 0.f;
    float h2n = 0.f;

    for (int tb = 0; tb < T_LEN; tb += 32) {
        float xv = xp[tb + lane];   // coalesced stripe of 32 timesteps

#pragma unroll 1
        for (int s = 0; s < 32; s++) {
            u64 xx = packdup(__shfl_sync(FULLM, xv, s));

            // ---------- layer 0 (K=20, reg weights) ----------
            u64 aif = B0.x, ago = B0.y;
            ffma2(aif, xx, wx.x); ffma2(ago, xx, wx.y);
            mac10_reg(aif, ago, h0s, wr0);
            float h0n = cellup(aif, ago, c0);
            h0s[j] = make_float2(h0n, h0n);
            __syncwarp();

            // ---------- layer 1 (K=40: h0 via reg weights, h1 via smem) ----------
            aif = B1.x; ago = B1.y;
            mac10_reg(aif, ago, h0s, wr1);
            mac10_sm(aif, ago, h1s, s_w1b, j);
            float h1n = cellup(aif, ago, c1);
            h1s[j] = make_float2(h1n, h1n);
            __syncwarp();

            // ---------- layer 2 (K=40: smem weights) ----------
            aif = B2.x; ago = B2.y;
            mac10_sm(aif, ago, h1s, s_w2, j);
            mac10_sm(aif, ago, h2s, s_w2 + HID, j);
            h2n = cellup(aif, ago, c2);
            h2s[j] = make_float2(h2n, h2n);
            // h2 first re-read after next iteration's two __syncwarps: ordered.
        }
    }

    // ---- final FC: out[b] = fc_w @ h2 + fc_b (reduce lanes 0..19) ----
    float p0 = (lane < HID) ? h2n * s_fcw[0][j] : 0.f;
    float p1 = (lane < HID) ? h2n * s_fcw[1][j] : 0.f;
#pragma unroll
    for (int off = 16; off > 0; off >>= 1) {
        p0 += __shfl_xor_sync(FULLM, p0, off);
        p1 += __shfl_xor_sync(FULLM, p1, off);
    }
    if (lane == 0) {
        out[b * 2 + 0] = p0 + s_fcb[0];
        out[b * 2 + 1] = p1 + s_fcb[1];
    }
}

extern "C" void kernel_launch(void* const* d_in, const int* in_sizes, int n_in,
                              void* d_out, int out_size) {
    const float* x    = (const float*)d_in[0];
    const float* wih0 = (const float*)d_in[1];
    const float* whh0 = (const float*)d_in[2];
    const float* bih0 = (const float*)d_in[3];
    const float* bhh0 = (const float*)d_in[4];
    const float* wih1 = (const float*)d_in[5];
    const float* whh1 = (const float*)d_in[6];
    const float* bih1 = (const float*)d_in[7];
    const float* bhh1 = (const float*)d_in[8];
    const float* wih2 = (const float*)d_in[9];
    const float* whh2 = (const float*)d_in[10];
    const float* bih2 = (const float*)d_in[11];
    const float* bhh2 = (const float*)d_in[12];
    const float* fcw  = (const float*)d_in[13];
    const float* fcb  = (const float*)d_in[14];
    float* out = (float*)d_out;

    // 148 blocks (1 per SM) x 7 warps: 1036 warp slots for 1024 batches
    lstm3_kernel<<<NBLOCKS, WARPS_PER_BLOCK * 32>>>(
        x, wih0, whh0, bih0, bhh0,
        wih1, whh1, bih1, bhh1,
        wih2, whh2, bih2, bhh2,
        fcw, fcb, out);
}

// round 8
// speedup vs baseline: 1.0935x; 1.0265x over previous
#include <cuda_runtime.h>
#include <cuda_bf16.h>

// 3-layer LSTM, B=1024, T=1024, H=20, IN=1, OUT=2, FC on last h2.
// R8: layer-specialized systolic pipeline. Each warp owns ONE layer with ALL
// its weights register-resident (k-pair packed for fma.rn.f32x2); layers are
// skewed by one timestep and hand h through SMEM double buffers with one
// __syncthreads per step. Block = 192 thr = 2 pipelines x {L0,L1,L2} x 4 batches.
// Grid = 128 (1 block/SM). Weight SMEM traffic in the hot loop: ZERO.

#define T_LEN 1024
#define HID   20
#define GB    4          // batches per pipeline
#define NW    6          // warps per block
#define FULLM 0xffffffffu

typedef unsigned long long u64;

__device__ __forceinline__ void ffma2(u64 &acc, u64 a, u64 b) {
    asm("fma.rn.f32x2 %0, %1, %2, %0;" : "+l"(acc) : "l"(a), "l"(b));
}
__device__ __forceinline__ u64 pack2f(float lo, float hi) {
    u64 r; asm("mov.b64 %0, {%1, %2};" : "=l"(r) : "f"(lo), "f"(hi)); return r;
}
__device__ __forceinline__ void unpack2(float &lo, float &hi, u64 v) {
    asm("mov.b64 {%0, %1}, %2;" : "=f"(lo), "=f"(hi) : "l"(v));
}

// ---- accurate fast activations (MUFU EX2/RCP, ~1e-6 err) ----
__device__ __forceinline__ float fsig(float x) {
    float e = __expf(-x);
    return __fdividef(1.0f, 1.0f + e);
}
__device__ __forceinline__ float ftanh(float x) {
    float ax = fabsf(x);
    float e  = __expf(-2.0f * ax);
    float r  = __fdividef(1.0f - e, 1.0f + e);
    return copysignf(r, x);
}
__device__ __forceinline__ float cellup(float pi, float pf, float pg, float po,
                                        float &c) {
    c = fsig(pf) * c + fsig(pi) * ftanh(pg);
    return fsig(po) * ftanh(c);
}

// 20 k-steps (5 float4 broadcast loads) against register weights W[g*10+m]
__device__ __forceinline__ void mac5(u64 &a0, u64 &a1, u64 &a2, u64 &a3,
                                     const float4* __restrict__ hbuf,
                                     const u64* __restrict__ W)
{
    const ulonglong2* q = (const ulonglong2*)hbuf;
#pragma unroll
    for (int i = 0; i < 5; i++) {
        ulonglong2 v = q[i];              // {h4i,h4i+1},{h4i+2,h4i+3}
        ffma2(a0, v.x, W[2*i]);      ffma2(a1, v.x, W[10 + 2*i]);
        ffma2(a2, v.x, W[20 + 2*i]); ffma2(a3, v.x, W[30 + 2*i]);
        ffma2(a0, v.y, W[2*i + 1]);      ffma2(a1, v.y, W[10 + 2*i + 1]);
        ffma2(a2, v.y, W[20 + 2*i + 1]); ffma2(a3, v.y, W[30 + 2*i + 1]);
    }
}

__global__ void __launch_bounds__(NW * 32, 1)
lstm3_pipe(const float* __restrict__ x,
           const float* __restrict__ wih0, const float* __restrict__ whh0,
           const float* __restrict__ bih0, const float* __restrict__ bhh0,
           const float* __restrict__ wih1, const float* __restrict__ whh1,
           const float* __restrict__ bih1, const float* __restrict__ bhh1,
           const float* __restrict__ wih2, const float* __restrict__ whh2,
           const float* __restrict__ bih2, const float* __restrict__ bhh2,
           const float* __restrict__ fcw,  const float* __restrict__ fcb,
           float* __restrict__ out)
{
    // h buffers: [layer][pipe][parity][batch][5 x float4 = 20 floats]
    __shared__ float4 s_h[3][2][2][GB][5];

    const int tid  = threadIdx.x;
    const int lane = tid & 31;
    const int wid  = tid >> 5;

    // zero all h buffers (both parities)
    {
        float4* p = &s_h[0][0][0][0][0];
        for (int i = tid; i < 3 * 2 * 2 * GB * 5; i += NW * 32)
            p[i] = make_float4(0.f, 0.f, 0.f, 0.f);
    }
    __syncthreads();

    // role map balances SMSPs (wid%4): S0={L1p0,L0p0} S1={L2p0,L0p1} S2={L1p1} S3={L2p1}
    int role, pipe;
    if (wid < 4) { role = 1 + (wid & 1); pipe = wid >> 1; }
    else         { role = 0;             pipe = wid - 4;  }

    const int j     = (lane < HID) ? lane : (HID - 1);  // lanes 20..31 shadow unit 19
    const int bbase = blockIdx.x * (2 * GB) + pipe * GB;

    // ---- register-resident weights (k-pair packed per gate) ----
    u64   W[80];
    float wx4[4];
    u64   Binit[4];
    if (role == 0) {
#pragma unroll
        for (int g = 0; g < 4; g++) {
            const float* wr = whh0 + (g * HID + j) * HID;
#pragma unroll
            for (int m = 0; m < 10; m++) W[g * 10 + m] = *(const u64*)(wr + 2 * m);
            wx4[g]   = wih0[g * HID + j];
            Binit[g] = pack2f(bih0[g * HID + j] + bhh0[g * HID + j], 0.f);
        }
    } else {
        const float* wi = (role == 1) ? wih1 : wih2;
        const float* wh = (role == 1) ? whh1 : whh2;
        const float* bi = (role == 1) ? bih1 : bih2;
        const float* bh = (role == 1) ? bhh1 : bhh2;
#pragma unroll
        for (int g = 0; g < 4; g++) {
            const float* wr1 = wi + (g * HID + j) * HID;
            const float* wr2 = wh + (g * HID + j) * HID;
#pragma unroll
            for (int m = 0; m < 10; m++) {
                W[     g * 10 + m] = *(const u64*)(wr1 + 2 * m);
                W[40 + g * 10 + m] = *(const u64*)(wr2 + 2 * m);
            }
            Binit[g] = pack2f(bi[g * HID + j] + bh[g * HID + j], 0.f);
        }
    }

    float cst[GB] = {0.f, 0.f, 0.f, 0.f};
    float xs[GB];

    // pipeline: step n -> L0 computes t=n, L1 t=n-1, L2 t=n-2
    for (int n = 0; n <= T_LEN + 1; n++) {
        if (role == 0) {
            if (n < T_LEN) {
                if ((n & 31) == 0) {
#pragma unroll
                    for (int gb = 0; gb < GB; gb++)
                        xs[gb] = x[(bbase + gb) * T_LEN + n + lane];  // coalesced stripe
                }
                const int pw = n & 1, pr = pw ^ 1;
#pragma unroll
                for (int gb = 0; gb < GB; gb++) {
                    float xv = __shfl_sync(FULLM, xs[gb], n & 31);
                    u64 a0 = Binit[0], a1 = Binit[1], a2 = Binit[2], a3 = Binit[3];
                    mac5(a0, a1, a2, a3, s_h[0][pipe][pr][gb], W);
                    float lo, hi, pi, pf, pg, po;
                    unpack2(lo, hi, a0); pi = lo + hi + xv * wx4[0];
                    unpack2(lo, hi, a1); pf = lo + hi + xv * wx4[1];
                    unpack2(lo, hi, a2); pg = lo + hi + xv * wx4[2];
                    unpack2(lo, hi, a3); po = lo + hi + xv * wx4[3];
                    float hn = cellup(pi, pf, pg, po, cst[gb]);
                    if (lane < HID) ((float*)s_h[0][pipe][pw][gb])[lane] = hn;
                }
            }
        } else if (role == 1) {
            if (n >= 1 && n <= T_LEN) {
                const int t = n - 1, pw = t & 1, pr = pw ^ 1;
#pragma unroll
                for (int gb = 0; gb < GB; gb++) {
                    u64 a0 = Binit[0], a1 = Binit[1], a2 = Binit[2], a3 = Binit[3];
                    mac5(a0, a1, a2, a3, s_h[0][pipe][pw][gb], W);       // h0[t]
                    mac5(a0, a1, a2, a3, s_h[1][pipe][pr][gb], W + 40);  // h1[t-1]
                    float lo, hi, pi, pf, pg, po;
                    unpack2(lo, hi, a0); pi = lo + hi;
                    unpack2(lo, hi, a1); pf = lo + hi;
                    unpack2(lo, hi, a2); pg = lo + hi;
                    unpack2(lo, hi, a3); po = lo + hi;
                    float hn = cellup(pi, pf, pg, po, cst[gb]);
                    if (lane < HID) ((float*)s_h[1][pipe][pw][gb])[lane] = hn;
                }
            }
        } else {
            if (n >= 2) {
                const int t = n - 2, pw = t & 1, pr = pw ^ 1;
#pragma unroll
                for (int gb = 0; gb < GB; gb++) {
                    u64 a0 = Binit[0], a1 = Binit[1], a2 = Binit[2], a3 = Binit[3];
                    mac5(a0, a1, a2, a3, s_h[1][pipe][pw][gb], W);       // h1[t]
                    mac5(a0, a1, a2, a3, s_h[2][pipe][pr][gb], W + 40);  // h2[t-1]
                    float lo, hi, pi, pf, pg, po;
                    unpack2(lo, hi, a0); pi = lo + hi;
                    unpack2(lo, hi, a1); pf = lo + hi;
                    unpack2(lo, hi, a2); pg = lo + hi;
                    unpack2(lo, hi, a3); po = lo + hi;
                    float hn = cellup(pi, pf, pg, po, cst[gb]);
                    if (lane < HID) ((float*)s_h[2][pipe][pw][gb])[lane] = hn;
                }
            }
        }
        __syncthreads();
    }

    // ---- final FC on h2[T-1] by the L2 warps ----
    if (role == 2) {
        const int pfin = (T_LEN - 1) & 1;
#pragma unroll
        for (int gb = 0; gb < GB; gb++) {
            float hv = ((const float*)s_h[2][pipe][pfin][gb])[j];
            float p0 = (lane < HID) ? hv * fcw[j]       : 0.f;
            float p1 = (lane < HID) ? hv * fcw[HID + j] : 0.f;
#pragma unroll
            for (int off = 16; off > 0; off >>= 1) {
                p0 += __shfl_xor_sync(FULLM, p0, off);
                p1 += __shfl_xor_sync(FULLM, p1, off);
            }
            if (lane == 0) {
                out[(bbase + gb) * 2 + 0] = p0 + fcb[0];
                out[(bbase + gb) * 2 + 1] = p1 + fcb[1];
            }
        }
    }
}

extern "C" void kernel_launch(void* const* d_in, const int* in_sizes, int n_in,
                              void* d_out, int out_size) {
    const float* x    = (const float*)d_in[0];
    const float* wih0 = (const float*)d_in[1];
    const float* whh0 = (const float*)d_in[2];
    const float* bih0 = (const float*)d_in[3];
    const float* bhh0 = (const float*)d_in[4];
    const float* wih1 = (const float*)d_in[5];
    const float* whh1 = (const float*)d_in[6];
    const float* bih1 = (const float*)d_in[7];
    const float* bhh1 = (const float*)d_in[8];
    const float* wih2 = (const float*)d_in[9];
    const float* whh2 = (const float*)d_in[10];
    const float* bih2 = (const float*)d_in[11];
    const float* bhh2 = (const float*)d_in[12];
    const float* fcw  = (const float*)d_in[13];
    const float* fcb  = (const float*)d_in[14];
    float* out = (float*)d_out;

    // 1024 batches / (2 pipelines x 4 batches) = 128 blocks of 192 threads
    lstm3_pipe<<<128, NW * 32>>>(x, wih0, whh0, bih0, bhh0,
                                 wih1, whh1, bih1, bhh1,
                                 wih2, whh2, bih2, bhh2,
                                 fcw, fcb, out);
}